// round 4
// baseline (speedup 1.0000x reference)
#include <cuda_runtime.h>
#include <cstdint>
#include <cstddef>

#define BB 16
#define SS 4096
#define DD 256
#define CL 8
#define NROWW 16
#define WGID 16
#define WSID 17
#define WLID 18
#define NTHREADS 608          // 16 row warps + G + S + loader
#define RING 64
#define XD 8                  // x smem ring depth
#define XPIPE 6               // cp.async groups in flight
#define LAGF 16               // fold application lag (steps)

// per-(b,t): {c = eta*(1-1/n)/n,  d = 2*alpha*c + c^2*||x||^2}
__device__ float2 g_cd[BB * SS + 8];
__device__ float  g_G0;       // ||M_init||_F^2

// ---------------- helpers --------------------------------------------------
__device__ __forceinline__ unsigned long long mul2(unsigned long long a, unsigned long long b) {
    unsigned long long d; asm("mul.rn.f32x2 %0,%1,%2;" : "=l"(d) : "l"(a), "l"(b)); return d;
}
__device__ __forceinline__ unsigned long long fma2(unsigned long long a, unsigned long long b, unsigned long long c) {
    unsigned long long d; asm("fma.rn.f32x2 %0,%1,%2,%3;" : "=l"(d) : "l"(a), "l"(b), "l"(c)); return d;
}
__device__ __forceinline__ unsigned long long add2(unsigned long long a, unsigned long long b) {
    unsigned long long d; asm("add.rn.f32x2 %0,%1,%2;" : "=l"(d) : "l"(a), "l"(b)); return d;
}
__device__ __forceinline__ void unpk(unsigned long long a, float& x, float& y) {
    asm("mov.b64 {%0,%1},%2;" : "=f"(x), "=f"(y) : "l"(a));
}
__device__ __forceinline__ unsigned long long pk(float lo, float hi) {
    unsigned long long d; asm("mov.b64 %0,{%1,%2};" : "=l"(d) : "f"(lo), "f"(hi)); return d;
}
__device__ __forceinline__ unsigned long long pack_fu(float v, unsigned tag) {
    return (unsigned long long)__float_as_uint(v) | ((unsigned long long)tag << 32);
}
__device__ __forceinline__ unsigned long long ldsv64(uint32_t a) {
    unsigned long long v; asm volatile("ld.volatile.shared.b64 %0,[%1];" : "=l"(v) : "r"(a) : "memory"); return v;
}
__device__ __forceinline__ void stsv64(uint32_t a, unsigned long long v) {
    asm volatile("st.volatile.shared.b64 [%0],%1;" :: "r"(a), "l"(v) : "memory");
}
__device__ __forceinline__ unsigned ldsv32(uint32_t a) {
    unsigned v; asm volatile("ld.volatile.shared.b32 %0,[%1];" : "=r"(v) : "r"(a) : "memory"); return v;
}
__device__ __forceinline__ void stsv32(uint32_t a, unsigned v) {
    asm volatile("st.volatile.shared.b32 [%0],%1;" :: "r"(a), "r"(v) : "memory");
}
__device__ __forceinline__ void stcl64(uint32_t a, unsigned long long v) {
    asm volatile("st.shared::cluster.b64 [%0],%1;" :: "r"(a), "l"(v) : "memory");
}
__device__ __forceinline__ void poll_eq32(uint32_t a, unsigned want) {
    if (ldsv32(a) == want) return;
    while (ldsv32(a) != want) __nanosleep(20);
}
__device__ __forceinline__ float poll_tag64(uint32_t a, unsigned want) {
    unsigned long long u = ldsv64(a);
    while ((unsigned)(u >> 32) != want) { __nanosleep(20); u = ldsv64(a); }
    return __uint_as_float((unsigned)u);
}
__device__ __forceinline__ void cpa16(uint32_t d, const void* s) {
    asm volatile("cp.async.ca.shared.global [%0],[%1],16;" :: "r"(d), "l"(s));
}
__device__ __forceinline__ void cpa8(uint32_t d, const void* s) {
    asm volatile("cp.async.ca.shared.global [%0],[%1],8;" :: "r"(d), "l"(s));
}

// ---------------------------------------------------------------------------
__global__ void coef_kernel(const float* __restrict__ x,
                            const float* __restrict__ eta_raw,
                            const float* __restrict__ alpha_raw) {
    float eta   = 0.2f / (1.0f + __expf(-eta_raw[0]));
    float alpha = 0.5f + 0.5f / (1.0f + __expf(-alpha_raw[0]));
    int warp  = (blockIdx.x * blockDim.x + threadIdx.x) >> 5;
    int lane  = threadIdx.x & 31;
    int nwarp = (gridDim.x * blockDim.x) >> 5;
    for (int row = warp; row < BB * SS; row += nwarp) {
        const float4* xr = reinterpret_cast<const float4*>(x + (size_t)row * DD);
        float4 a = xr[lane];
        float4 b = xr[lane + 32];
        float ss = a.x*a.x + a.y*a.y + a.z*a.z + a.w*a.w
                 + b.x*b.x + b.y*b.y + b.z*b.z + b.w*b.w;
        #pragma unroll
        for (int k = 16; k; k >>= 1) ss += __shfl_xor_sync(0xffffffffu, ss, k);
        if (lane == 0) {
            float n   = fmaxf(sqrtf(ss), 1e-6f);
            float inv = 1.0f / n;
            float c   = eta * (1.0f - inv) * inv;
            float2 cd; cd.x = c; cd.y = 2.0f * alpha * c + c * c * ss;
            g_cd[row] = cd;
        }
    }
}

__global__ void g0_kernel(const float* __restrict__ M) {
    __shared__ float red[32];
    int tid = threadIdx.x;
    float s = 0.0f;
    for (int i = tid; i < DD * DD; i += 1024) { float v = M[i]; s = fmaf(v, v, s); }
    #pragma unroll
    for (int k = 16; k; k >>= 1) s += __shfl_xor_sync(0xffffffffu, s, k);
    if ((tid & 31) == 0) red[tid >> 5] = s;
    __syncthreads();
    if (tid < 32) {
        float v = red[tid];
        #pragma unroll
        for (int k = 16; k; k >>= 1) v += __shfl_xor_sync(0xffffffffu, v, k);
        if (tid == 0) g_G0 = v;
    }
}

// ---------------------------------------------------------------------------
// Persistent scan. 8-CTA cluster per batch. Roles per CTA:
//   warps 0-15 : hold M rows (row = rank*32 + wid*2 + (lane>>4); each lane owns
//                16 cols as 8 f32x2 pairs, strided for conflict-free LDS.64)
//   warp 16 (G): gathers per-warp ||w||^2 partials, DSMEM-multicasts CTA sum,
//                publishes progress counter (loader backpressure)
//   warp 17 (S): consumes 8 CTA partials, scalar (P,G,s) recurrence, writes
//                coalesced outputs, publishes scheduled fold factors
//   warp 18 (L): cp.async stages x_t and (c,d) into smem rings, 6 deep
// ---------------------------------------------------------------------------
__global__ void __cluster_dims__(CL, 1, 1) __launch_bounds__(NTHREADS, 1)
scan_kernel(const float* __restrict__ x,
            const float* __restrict__ Minit,
            const float* __restrict__ alpha_raw,
            float* __restrict__ out) {
    __shared__ __align__(16) float xs[XD][DD];       // 8 KB  x ring
    __shared__ float2 cdr[RING];                     // (c,d) ring
    __shared__ unsigned long long wv[RING][32];      // {tag, w_row}
    __shared__ unsigned long long zv[RING][NROWW];   // {tag, w0^2+w1^2}
    __shared__ unsigned long long cslot[RING][CL];   // {tag, CTA ||w||^2 partial}
    __shared__ unsigned long long resf[8];           // {tag j+1, fold factor}
    __shared__ unsigned long long finslot;           // {tagF, final scale}
    __shared__ unsigned int xready[XD];              // x slot tags
    __shared__ unsigned int gprog;                   // G progress (steps done)

    unsigned rank; asm("mov.u32 %0, %%cluster_ctarank;" : "=r"(rank));
    int batch = blockIdx.x / CL;
    int tid   = threadIdx.x;
    int wid   = tid >> 5;
    int lane  = tid & 31;

    for (int i = tid; i < RING * 32;    i += NTHREADS) (&wv[0][0])[i]    = 0ull;
    for (int i = tid; i < RING * NROWW; i += NTHREADS) (&zv[0][0])[i]    = 0ull;
    for (int i = tid; i < RING * CL;    i += NTHREADS) (&cslot[0][0])[i] = 0ull;
    if (tid < 8)  resf[tid] = 0ull;
    if (tid < XD) xready[tid] = 0u;
    if (tid == 0) { finslot = 0ull; gprog = 0u; }
    __syncthreads();
    asm volatile("barrier.cluster.arrive.aligned;" ::: "memory");
    asm volatile("barrier.cluster.wait.aligned;"   ::: "memory");

    float alpha = 0.5f + 0.5f / (1.0f + __expf(-alpha_raw[0]));

    uint32_t wv_b   = (uint32_t)__cvta_generic_to_shared(&wv[0][0]);
    uint32_t zv_b   = (uint32_t)__cvta_generic_to_shared(&zv[0][0]);
    uint32_t cs_b   = (uint32_t)__cvta_generic_to_shared(&cslot[0][0]);
    uint32_t rf_b   = (uint32_t)__cvta_generic_to_shared(&resf[0]);
    uint32_t fin_b  = (uint32_t)__cvta_generic_to_shared(&finslot);
    uint32_t xr_b   = (uint32_t)__cvta_generic_to_shared(&xready[0]);
    uint32_t gp_b   = (uint32_t)__cvta_generic_to_shared(&gprog);

    if (wid < NROWW) {
        // ===================== row warp =====================
        int h = lane >> 4, i = lane & 15;
        int row = (int)rank * 32 + wid * 2 + h;
        unsigned long long m[8];
        {
            const unsigned long long* Mr =
                (const unsigned long long*)(Minit + (size_t)row * DD);
            #pragma unroll
            for (int j = 0; j < 8; j++) m[j] = Mr[i + 16 * j];   // cols 2i+32j, +1
        }
        unsigned long long alpha2 = pk(alpha, alpha);
        uint32_t wv_me = wv_b + (uint32_t)(wid * 2 + h) * 8u;
        uint32_t zv_me = zv_b + (uint32_t)wid * 8u;

        // preload x_0, c_0
        unsigned long long xc[8]; float c_c;
        poll_eq32(xr_b + 0u, 1u);
        {
            const unsigned long long* p = (const unsigned long long*)&xs[0][0];
            #pragma unroll
            for (int j = 0; j < 8; j++) xc[j] = p[i + 16 * j];
            c_c = cdr[0].x;
        }

        #pragma unroll 2
        for (int t = 0; t < SS; t++) {
            unsigned long long xn[8]; float c_n = 0.0f;
            if (t + 1 < SS) {
                poll_eq32(xr_b + (uint32_t)((t + 1) & (XD - 1)) * 4u, (unsigned)(t + 2));
                const unsigned long long* p =
                    (const unsigned long long*)&xs[(t + 1) & (XD - 1)][0];
                #pragma unroll
                for (int j = 0; j < 8; j++) xn[j] = p[i + 16 * j];
                c_n = cdr[(t + 1) & (RING - 1)].x;
            }
            // matvec
            unsigned long long a0 = mul2(m[0], xc[0]), a1 = mul2(m[1], xc[1]);
            a0 = fma2(m[2], xc[2], a0); a1 = fma2(m[3], xc[3], a1);
            a0 = fma2(m[4], xc[4], a0); a1 = fma2(m[5], xc[5], a1);
            a0 = fma2(m[6], xc[6], a0); a1 = fma2(m[7], xc[7], a1);
            float lo, hi; unpk(add2(a0, a1), lo, hi);
            float w = lo + hi;
            #pragma unroll
            for (int k = 8; k; k >>= 1) w += __shfl_xor_sync(0xffffffffu, w, k);

            int slot = t & (RING - 1);
            if (i == 0)   // lanes 0 and 16
                stsv64(wv_me + (uint32_t)slot * 256u, pack_fu(w, (unsigned)(t + 1)));
            float u = __shfl_xor_sync(0xffffffffu, w, 16);
            if (lane == 0)
                stsv64(zv_me + (uint32_t)slot * (NROWW * 8u),
                       pack_fu(fmaf(w, w, u * u), (unsigned)(t + 1)));

            // update: m = alpha*m + (c*w)*x
            float g = c_c * w;
            unsigned long long g2 = pk(g, g);
            #pragma unroll
            for (int j = 0; j < 8; j++) m[j] = fma2(g2, xc[j], mul2(alpha2, m[j]));

            // scheduled fold: at t = 32j+47 apply factor published for fold j
            if ((t & 31) == 15 && t >= 47) {
                int jj = (t - 47) >> 5;
                float f = poll_tag64(rf_b + (uint32_t)(jj & 7) * 8u, (unsigned)(jj + 1));
                unsigned long long f2 = pk(f, f);
                #pragma unroll
                for (int j = 0; j < 8; j++) m[j] = mul2(f2, m[j]);
            }
            #pragma unroll
            for (int j = 0; j < 8; j++) xc[j] = xn[j];
            c_c = c_n;
        }
        // final scale -> M_final
        float Pf = poll_tag64(fin_b, 0x7fffffffu);
        unsigned long long p2 = pk(Pf, Pf);
        unsigned long long* Mo = (unsigned long long*)
            (out + (size_t)BB * SS * DD + (size_t)batch * DD * DD + (size_t)row * DD);
        #pragma unroll
        for (int j = 0; j < 8; j++) Mo[i + 16 * j] = mul2(p2, m[j]);

    } else if (wid == WGID) {
        // ===================== G warp =====================
        uint32_t raddr = 0;
        {
            uint32_t cb = (uint32_t)__cvta_generic_to_shared(&cslot[0][rank]);
            if (lane < CL)
                asm("mapa.shared::cluster.u32 %0,%1,%2;" : "=r"(raddr) : "r"(cb), "r"(lane));
        }
        for (int t = 0; t < SS; t++) {
            int slot = t & (RING - 1);
            float z = 0.0f;
            if (lane < NROWW)
                z = poll_tag64(zv_b + (uint32_t)(slot * NROWW + lane) * 8u, (unsigned)(t + 1));
            #pragma unroll
            for (int k = 8; k; k >>= 1) z += __shfl_xor_sync(0xffffffffu, z, k);
            if (lane < CL)
                stcl64(raddr + (uint32_t)slot * (CL * 8u), pack_fu(z, (unsigned)(t + 1)));
            if (lane == 0) stsv32(gp_b, (unsigned)(t + 1));
        }

    } else if (wid == WSID) {
        // ===================== S warp =====================
        float P = 1.0f, G = g_G0;
        float aa = alpha * alpha;
        float pend_f = 1.0f; int pend_mat = -1;
        float* outb = out + (size_t)batch * SS * DD + rank * 32 + lane;
        for (int tau = 0; tau < SS; tau++) {
            int slot = tau & (RING - 1);
            float zc = 0.0f;
            if (lane < CL)
                zc = poll_tag64(cs_b + (uint32_t)(slot * CL + lane) * 8u, (unsigned)(tau + 1));
            #pragma unroll
            for (int k = 4; k; k >>= 1) zc += __shfl_xor_sync(0xffffffffu, zc, k);
            // lanes 0-7 now hold the global ||w||^2; lane 0 authoritative
            float w = poll_tag64(wv_b + (uint32_t)(slot * 32 + lane) * 8u, (unsigned)(tau + 1));
            float Qb = __shfl_sync(0xffffffffu, P, 0);     // P_{tau-1}
            outb[(size_t)tau * DD] = Qb * w;
            // scalar recurrence (lane 0 authoritative; others harmless)
            float y2 = Qb * Qb * zc;
            float d  = cdr[slot].y;
            float Gn = fmaf(aa, G, d * y2);
            float s  = fminf(15.0f / (sqrtf(Gn) + 1e-6f), 1.0f);
            G = s * s * Gn;
            P = Qb * s;
            if (tau == pend_mat) { P = P / pend_f; pend_mat = -1; }
            if ((tau & 31) == 31 && tau + LAGF <= SS - 1) {
                int jj = tau >> 5;
                pend_f = __shfl_sync(0xffffffffu, P, 0);
                P = pend_f;                 // keep lanes consistent
                pend_mat = tau + LAGF;
                if (lane == 0)
                    stsv64(rf_b + (uint32_t)(jj & 7) * 8u, pack_fu(P, (unsigned)(jj + 1)));
            }
        }
        if (lane == 0) {
            float Pf = P;
            stsv64(fin_b, pack_fu(Pf, 0x7fffffffu));
        }

    } else {
        // ===================== loader warp =====================
        const char*   xsrc = (const char*)(x + (size_t)batch * SS * DD);
        const float2* cdsrc = g_cd + (size_t)batch * SS;
        for (int tf = 0; tf < SS; tf++) {
            while ((int)ldsv32(gp_b) < tf - 7) __nanosleep(40);
            uint32_t dst = (uint32_t)__cvta_generic_to_shared(&xs[tf & (XD - 1)][0]) + lane * 16u;
            const char* src = xsrc + (size_t)tf * (DD * 4) + lane * 16;
            cpa16(dst, src);
            cpa16(dst + 512u, src + 512);
            if (lane == 0)
                cpa8((uint32_t)__cvta_generic_to_shared(&cdr[tf & (RING - 1)]), cdsrc + tf);
            asm volatile("cp.async.commit_group;" ::: "memory");
            if (tf >= XPIPE - 1) {
                asm volatile("cp.async.wait_group %0;" :: "n"(XPIPE) : "memory");
                asm volatile("membar.cta;" ::: "memory");
                int pf = tf - XPIPE;   // completed >= tf+1-XPIPE, post pf = tf-XPIPE
                if (pf >= 0 && lane == 0)
                    stsv32(xr_b + (uint32_t)(pf & (XD - 1)) * 4u, (unsigned)(pf + 1));
            }
        }
        asm volatile("cp.async.wait_group 0;" ::: "memory");
        asm volatile("membar.cta;" ::: "memory");
        if (lane == 0) {
            for (int pf = SS - XPIPE; pf < SS; pf++)
                if (pf >= 0)
                    stsv32(xr_b + (uint32_t)(pf & (XD - 1)) * 4u, (unsigned)(pf + 1));
        }
    }
}

// ---------------------------------------------------------------------------
extern "C" void kernel_launch(void* const* d_in, const int* in_sizes, int n_in,
                              void* d_out, int out_size) {
    const float* x         = (const float*)d_in[0];
    const float* M_init    = (const float*)d_in[1];
    const float* eta_raw   = (const float*)d_in[2];
    const float* alpha_raw = (const float*)d_in[3];
    float*       out       = (float*)d_out;

    coef_kernel<<<1024, 256>>>(x, eta_raw, alpha_raw);
    g0_kernel<<<1, 1024>>>(M_init);
    scan_kernel<<<BB * CL, NTHREADS>>>(x, M_init, alpha_raw, out);
}

// round 5
// speedup vs baseline: 2.2731x; 2.2731x over previous
#include <cuda_runtime.h>
#include <cstdint>
#include <cstddef>

#define BB 16
#define SS 4096
#define DD 256
#define CL 8
#define NROWW 16
#define NTHREADS 576          // wid0=G, wid1=S, wid2..17 = 16 row warps
#define RING 64
#define LAGF 16               // fold application lag (steps)

typedef unsigned long long ull;

// per-(b,t): {c = eta*(1-1/n)/n,  d = 2*alpha*c + c^2*||x||^2}
__device__ float2 g_cd[BB * SS + 8];
__device__ float  g_G0;       // ||M_init||_F^2

// ---------------- helpers --------------------------------------------------
__device__ __forceinline__ ull mul2(ull a, ull b) {
    ull d; asm("mul.rn.f32x2 %0,%1,%2;" : "=l"(d) : "l"(a), "l"(b)); return d;
}
__device__ __forceinline__ ull fma2(ull a, ull b, ull c) {
    ull d; asm("fma.rn.f32x2 %0,%1,%2,%3;" : "=l"(d) : "l"(a), "l"(b), "l"(c)); return d;
}
__device__ __forceinline__ ull add2(ull a, ull b) {
    ull d; asm("add.rn.f32x2 %0,%1,%2;" : "=l"(d) : "l"(a), "l"(b)); return d;
}
__device__ __forceinline__ void unpk(ull a, float& x, float& y) {
    asm("mov.b64 {%0,%1},%2;" : "=f"(x), "=f"(y) : "l"(a));
}
__device__ __forceinline__ ull pk(float lo, float hi) {
    ull d; asm("mov.b64 %0,{%1,%2};" : "=l"(d) : "f"(lo), "f"(hi)); return d;
}
__device__ __forceinline__ ull pack_fu(float v, unsigned tag) {
    return (ull)__float_as_uint(v) | ((ull)tag << 32);
}
__device__ __forceinline__ ull ldsv64(uint32_t a) {
    ull v; asm volatile("ld.volatile.shared.b64 %0,[%1];" : "=l"(v) : "r"(a) : "memory"); return v;
}
__device__ __forceinline__ void stsv64(uint32_t a, ull v) {
    asm volatile("st.volatile.shared.b64 [%0],%1;" :: "r"(a), "l"(v) : "memory");
}
__device__ __forceinline__ void stcl64(uint32_t a, ull v) {
    asm volatile("st.shared::cluster.b64 [%0],%1;" :: "r"(a), "l"(v) : "memory");
}
__device__ __forceinline__ float poll_tag64(uint32_t a, unsigned want) {
    ull u = ldsv64(a);
    while ((unsigned)(u >> 32) != want) { __nanosleep(20); u = ldsv64(a); }
    return __uint_as_float((unsigned)u);
}

// ---------------------------------------------------------------------------
__global__ void coef_kernel(const float* __restrict__ x,
                            const float* __restrict__ eta_raw,
                            const float* __restrict__ alpha_raw) {
    float eta   = 0.2f / (1.0f + __expf(-eta_raw[0]));
    float alpha = 0.5f + 0.5f / (1.0f + __expf(-alpha_raw[0]));
    int warp  = (blockIdx.x * blockDim.x + threadIdx.x) >> 5;
    int lane  = threadIdx.x & 31;
    int nwarp = (gridDim.x * blockDim.x) >> 5;
    for (int row = warp; row < BB * SS; row += nwarp) {
        const float4* xr = reinterpret_cast<const float4*>(x + (size_t)row * DD);
        float4 a = xr[lane];
        float4 b = xr[lane + 32];
        float ss = a.x*a.x + a.y*a.y + a.z*a.z + a.w*a.w
                 + b.x*b.x + b.y*b.y + b.z*b.z + b.w*b.w;
        #pragma unroll
        for (int k = 16; k; k >>= 1) ss += __shfl_xor_sync(0xffffffffu, ss, k);
        if (lane == 0) {
            float n   = fmaxf(sqrtf(ss), 1e-6f);
            float inv = 1.0f / n;
            float c   = eta * (1.0f - inv) * inv;
            float2 cd; cd.x = c; cd.y = 2.0f * alpha * c + c * c * ss;
            g_cd[row] = cd;
        }
    }
}

__global__ void g0_kernel(const float* __restrict__ M) {
    __shared__ float red[32];
    int tid = threadIdx.x;
    float s = 0.0f;
    for (int i = tid; i < DD * DD; i += 1024) { float v = M[i]; s = fmaf(v, v, s); }
    #pragma unroll
    for (int k = 16; k; k >>= 1) s += __shfl_xor_sync(0xffffffffu, s, k);
    if ((tid & 31) == 0) red[tid >> 5] = s;
    __syncthreads();
    if (tid < 32) {
        float v = red[tid];
        #pragma unroll
        for (int k = 16; k; k >>= 1) v += __shfl_xor_sync(0xffffffffu, v, k);
        if (tid == 0) g_G0 = v;
    }
}

// ---------------------------------------------------------------------------
// Persistent scan. 8-CTA cluster per batch.
//   wid 0 (G): gather 16 per-warp ||w||^2 partials, DSMEM-multicast CTA sum
//   wid 1 (S): consume 8 CTA partials, scalar (P,G,s) recurrence, coalesced
//              output writes, publish scheduled fold factors
//   wid 2-17 : row warps, 2 rows each; m~ = m/alpha^k in registers; poll-free
//              except one fold poll every 32 steps. x via lead-3 LDG pipeline.
// Helper warps at LOW wid => row warps win the hi-wid-first arbiter.
// ---------------------------------------------------------------------------
__global__ void __cluster_dims__(CL, 1, 1) __launch_bounds__(NTHREADS, 1)
scan_kernel(const float* __restrict__ x,
            const float* __restrict__ Minit,
            const float* __restrict__ alpha_raw,
            float* __restrict__ out) {
    __shared__ ull wv[RING][32];      // {tag, w_row} (true scale)
    __shared__ ull zv[RING][NROWW];   // {tag, w0^2+w1^2}
    __shared__ ull cslot[RING][CL];   // {tag, CTA ||w||^2 partial} (DSMEM in)
    __shared__ ull resf[8];           // {tag jj+1, fold factor}
    __shared__ ull finslot;           // {0x7fffffff, final pending scale}

    unsigned rank; asm("mov.u32 %0, %%cluster_ctarank;" : "=r"(rank));
    int batch = blockIdx.x / CL;
    int tid   = threadIdx.x;
    int wid   = tid >> 5;
    int lane  = tid & 31;

    for (int i = tid; i < RING * 32;    i += NTHREADS) (&wv[0][0])[i]    = 0ull;
    for (int i = tid; i < RING * NROWW; i += NTHREADS) (&zv[0][0])[i]    = 0ull;
    for (int i = tid; i < RING * CL;    i += NTHREADS) (&cslot[0][0])[i] = 0ull;
    if (tid < 8)  resf[tid] = 0ull;
    if (tid == 0) finslot = 0ull;
    __syncthreads();
    asm volatile("barrier.cluster.arrive.aligned;" ::: "memory");
    asm volatile("barrier.cluster.wait.aligned;"   ::: "memory");

    float alpha = 0.5f + 0.5f / (1.0f + __expf(-alpha_raw[0]));

    uint32_t wv_b  = (uint32_t)__cvta_generic_to_shared(&wv[0][0]);
    uint32_t zv_b  = (uint32_t)__cvta_generic_to_shared(&zv[0][0]);
    uint32_t cs_b  = (uint32_t)__cvta_generic_to_shared(&cslot[0][0]);
    uint32_t rf_b  = (uint32_t)__cvta_generic_to_shared(&resf[0]);
    uint32_t fin_b = (uint32_t)__cvta_generic_to_shared(&finslot);

    if (wid >= 2) {
        // ===================== row warp =====================
        int rw  = wid - 2;
        int rg0 = (int)rank * 32 + rw * 2;
        float inv_alpha = 1.0f / alpha;

        ull m0[4], m1[4];
        {
            const ulonglong2* mp = (const ulonglong2*)Minit + (size_t)rg0 * 64;
            ulonglong2 v0 = mp[lane],      v1 = mp[32 + lane];
            m0[0] = v0.x; m0[1] = v0.y; m0[2] = v1.x; m0[3] = v1.y;
            v0 = mp[64 + lane]; v1 = mp[96 + lane];
            m1[0] = v0.x; m1[1] = v0.y; m1[2] = v1.x; m1[3] = v1.y;
        }
        const ulonglong2* xbp = (const ulonglong2*)(x + (size_t)batch * SS * DD);
        const float* cb = (const float*)(g_cd + (size_t)batch * SS);  // c at [2t]

        ull xbuf[4][4]; float cbuf[4];
        #pragma unroll
        for (int p = 0; p < 3; p++) {
            const ulonglong2* xp = xbp + (size_t)p * 64;
            ulonglong2 v0 = xp[lane], v1 = xp[32 + lane];
            xbuf[p][0] = v0.x; xbuf[p][1] = v0.y; xbuf[p][2] = v1.x; xbuf[p][3] = v1.y;
            cbuf[p] = __ldg(cb + 2 * p);
        }

        float a_k = 1.0f, inv_a = 1.0f;
        uint32_t wv_me = wv_b + (uint32_t)(rw * 2) * 8u;
        uint32_t zv_me = zv_b + (uint32_t)rw * 8u;

        #pragma unroll 4
        for (int t = 0; t < SS; t++) {
            // prefetch x_{t+3}, c_{t+3} (lead 3; clamp at tail)
            {
                int tp = t + 3; if (tp > SS - 1) tp = SS - 1;
                int pb = (t + 3) & 3;
                const ulonglong2* xp = xbp + (size_t)tp * 64;
                ulonglong2 v0 = xp[lane], v1 = xp[32 + lane];
                xbuf[pb][0] = v0.x; xbuf[pb][1] = v0.y;
                xbuf[pb][2] = v1.x; xbuf[pb][3] = v1.y;
                cbuf[pb] = __ldg(cb + 2 * tp);
            }
            int cu = t & 3;
            // matvec on m~ (two 4-deep chains)
            ull a = mul2(m0[0], xbuf[cu][0]);
            a = fma2(m0[1], xbuf[cu][1], a);
            a = fma2(m0[2], xbuf[cu][2], a);
            a = fma2(m0[3], xbuf[cu][3], a);
            ull b = mul2(m1[0], xbuf[cu][0]);
            b = fma2(m1[1], xbuf[cu][1], b);
            b = fma2(m1[2], xbuf[cu][2], b);
            b = fma2(m1[3], xbuf[cu][3], b);
            float ax, ay, bx, by; unpk(a, ax, ay); unpk(b, bx, by);
            float wa = ax + ay, wb = bx + by;
            #pragma unroll
            for (int k = 16; k; k >>= 1) {
                wa += __shfl_xor_sync(0xffffffffu, wa, k);
                wb += __shfl_xor_sync(0xffffffffu, wb, k);
            }
            // true-scale w = alpha^k * (m~ . x)
            float wat = a_k * wa, wbt = a_k * wb;
            int slot = t & (RING - 1);
            if (lane == 0) {
                unsigned tg = (unsigned)(t + 1);
                stsv64(wv_me + (uint32_t)slot * 256u,      pack_fu(wat, tg));
                stsv64(wv_me + (uint32_t)slot * 256u + 8u, pack_fu(wbt, tg));
                stsv64(zv_me + (uint32_t)slot * (NROWW * 8u),
                       pack_fu(fmaf(wat, wat, wbt * wbt), tg));
            }
            // single-FMA update: m~ += (c*w/alpha^{k+1}) * x
            inv_a *= inv_alpha;
            a_k   *= alpha;
            float ci = cbuf[cu] * inv_a;
            float ga = ci * wat, gb = ci * wbt;
            ull g2a = pk(ga, ga), g2b = pk(gb, gb);
            #pragma unroll
            for (int j = 0; j < 4; j++) {
                m0[j] = fma2(g2a, xbuf[cu][j], m0[j]);
                m1[j] = fma2(g2b, xbuf[cu][j], m1[j]);
            }
            // scheduled refactor: fold f_jj * alpha^{k+1}, reset k
            if ((t & 31) == 15 && t >= 47) {
                int jj = (t - 47) >> 5;
                float f = 0.0f;
                if (lane == 0)
                    f = poll_tag64(rf_b + (uint32_t)(jj & 7) * 8u, (unsigned)(jj + 1));
                f = __shfl_sync(0xffffffffu, f, 0);
                float ft = f * a_k;
                ull f2 = pk(ft, ft);
                #pragma unroll
                for (int j = 0; j < 4; j++) { m0[j] = mul2(f2, m0[j]); m1[j] = mul2(f2, m1[j]); }
                a_k = 1.0f; inv_a = 1.0f;
            }
        }
        // M_final = Pf * alpha^k * m~
        float Pf = 0.0f;
        if (lane == 0) Pf = poll_tag64(fin_b, 0x7fffffffu);
        Pf = __shfl_sync(0xffffffffu, Pf, 0);
        float fs = Pf * a_k;
        ull p2 = pk(fs, fs);
        ulonglong2* mo = (ulonglong2*)
            (out + (size_t)BB * SS * DD + (size_t)batch * DD * DD) + (size_t)rg0 * 64;
        ulonglong2 sv;
        sv.x = mul2(p2, m0[0]); sv.y = mul2(p2, m0[1]); mo[lane]      = sv;
        sv.x = mul2(p2, m0[2]); sv.y = mul2(p2, m0[3]); mo[32 + lane] = sv;
        sv.x = mul2(p2, m1[0]); sv.y = mul2(p2, m1[1]); mo[64 + lane] = sv;
        sv.x = mul2(p2, m1[2]); sv.y = mul2(p2, m1[3]); mo[96 + lane] = sv;

    } else if (wid == 0) {
        // ===================== G warp =====================
        uint32_t raddr = 0;
        {
            uint32_t cb2 = (uint32_t)__cvta_generic_to_shared(&cslot[0][rank]);
            if (lane < CL)
                asm("mapa.shared::cluster.u32 %0,%1,%2;" : "=r"(raddr) : "r"(cb2), "r"(lane));
        }
        for (int t = 0; t < SS; t++) {
            int slot = t & (RING - 1);
            float z = 0.0f;
            if (lane < NROWW)
                z = poll_tag64(zv_b + (uint32_t)(slot * NROWW + lane) * 8u, (unsigned)(t + 1));
            #pragma unroll
            for (int k = 8; k; k >>= 1) z += __shfl_xor_sync(0xffffffffu, z, k);
            if (lane < CL)
                stcl64(raddr + (uint32_t)slot * (CL * 8u), pack_fu(z, (unsigned)(t + 1)));
        }

    } else {
        // ===================== S warp =====================
        const float* db = (const float*)(g_cd + (size_t)batch * SS) + 1;  // d at [2t+1]
        float P = 1.0f, G = g_G0;
        float aa = alpha * alpha;
        float pend_f = 1.0f; int pend_mat = -1;
        float* outb = out + (size_t)batch * SS * DD + rank * 32 + lane;
        for (int tau = 0; tau < SS; tau++) {
            int slot = tau & (RING - 1);
            float w = poll_tag64(wv_b + (uint32_t)(slot * 32 + lane) * 8u, (unsigned)(tau + 1));
            float zc = 0.0f;
            if (lane < CL)
                zc = poll_tag64(cs_b + (uint32_t)(slot * CL + lane) * 8u, (unsigned)(tau + 1));
            #pragma unroll
            for (int k = 4; k; k >>= 1) zc += __shfl_xor_sync(0xffffffffu, zc, k);
            float Qb = __shfl_sync(0xffffffffu, P, 0);   // scale for M_tau
            outb[(size_t)tau * DD] = Qb * w;
            float y2 = Qb * Qb * zc;
            float d  = __ldg(db + 2 * tau);
            float Gn = fmaf(aa, G, d * y2);
            float s  = fminf(15.0f / (sqrtf(Gn) + 1e-6f), 1.0f);
            G = s * s * Gn;
            P = Qb * s;
            if (tau == pend_mat) { P = P / pend_f; pend_mat = -1; }
            if ((tau & 31) == 31 && tau + LAGF <= SS - 1) {
                int jj = tau >> 5;
                pend_f = __shfl_sync(0xffffffffu, P, 0);
                P = pend_f;
                pend_mat = tau + LAGF;
                if (lane == 0)
                    stsv64(rf_b + (uint32_t)(jj & 7) * 8u, pack_fu(P, (unsigned)(jj + 1)));
            }
        }
        if (lane == 0) stsv64(fin_b, pack_fu(P, 0x7fffffffu));
    }
}

// ---------------------------------------------------------------------------
extern "C" void kernel_launch(void* const* d_in, const int* in_sizes, int n_in,
                              void* d_out, int out_size) {
    const float* x         = (const float*)d_in[0];
    const float* M_init    = (const float*)d_in[1];
    const float* eta_raw   = (const float*)d_in[2];
    const float* alpha_raw = (const float*)d_in[3];
    float*       out       = (float*)d_out;

    coef_kernel<<<1024, 256>>>(x, eta_raw, alpha_raw);
    g0_kernel<<<1, 1024>>>(M_init);
    scan_kernel<<<BB * CL, NTHREADS>>>(x, M_init, alpha_raw, out);
}